// round 15
// baseline (speedup 1.0000x reference)
#include <cuda_runtime.h>
#include <cstdint>

// FixedGaussianBlur: depthwise 21x21 Gaussian (sigma=3), reflect padding,
// x[32,3,512,512] f32 -> y[32,3,512,512] f32.
// R14/R12 skeleton (61.5us best: warp-owned rows, in-place streaming h-pass,
// 1 block barrier, FFMA2 col-pair vertical) with an LDG.128 interior loader:
// left halo read from x0-12 (16B aligned) -> 22 LDG.128/row (one issue round,
// MLP_p1 halved -> less cross-CTA L1tex-queue contention per B300 model).
// smem layout unchanged: col c <-> gmem x0-10+c, stride 84.

#define IMG_W 512
#define IMG_H 512
#define PAD 10
#define KS 21
#define TW 64
#define TH 128
#define SROWS 148
#define SCOLS 84
#define NTHREADS 512
#define NIMG 96
#define SMEM_BYTES (SROWS * SCOLS * 4)  // 49728

#define W0  0.13303900f
#define W1  0.12584950f
#define W2  0.10652928f
#define W3  0.08069223f
#define W4  0.05469397f
#define W5  0.03317359f
#define W6  0.01800488f
#define W7  0.00874446f
#define W8  0.00380033f
#define W9  0.00147793f
#define W10 0.00051432f

__device__ __forceinline__ float tap(int j) {
    constexpr float w[KS] = {W10, W9, W8, W7, W6, W5, W4, W3, W2, W1, W0,
                             W1, W2, W3, W4, W5, W6, W7, W8, W9, W10};
    return w[j];
}

__device__ __forceinline__ int reflect_idx(int i, int n) {
    i = (i < 0) ? -i : i;
    i = (i >= n) ? (2 * n - 2 - i) : i;
    return i;
}

__device__ __forceinline__ uint64_t bcast2(float f) {
    uint32_t b = __float_as_uint(f);
    return ((uint64_t)b << 32) | (uint64_t)b;
}

__device__ __forceinline__ void ffma2(uint64_t& d, uint64_t a, uint64_t b, uint64_t c) {
    asm("fma.rn.f32x2 %0, %1, %2, %3;" : "=l"(d) : "l"(a), "l"(b), "l"(c));
}

// Streaming 16-output horizontal filter: 9 LDS.128, each float4 consumed
// immediately into 16 accumulators (liveness ~25 regs).
__device__ __forceinline__ void hfilter16s(const float* srow, float o[16]) {
    #pragma unroll
    for (int c = 0; c < 16; ++c) o[c] = 0.0f;
    const float4* p = reinterpret_cast<const float4*>(srow);
    #pragma unroll
    for (int q = 0; q < 9; ++q) {
        float4 t4 = p[q];
        #pragma unroll
        for (int c = 0; c < 16; ++c) {
            int j0 = 4 * q + 0 - c;
            int j1 = 4 * q + 1 - c;
            int j2 = 4 * q + 2 - c;
            int j3 = 4 * q + 3 - c;
            if (j0 >= 0 && j0 < KS) o[c] = fmaf(t4.x, tap(j0), o[c]);
            if (j1 >= 0 && j1 < KS) o[c] = fmaf(t4.y, tap(j1), o[c]);
            if (j2 >= 0 && j2 < KS) o[c] = fmaf(t4.z, tap(j2), o[c]);
            if (j3 >= 0 && j3 < KS) o[c] = fmaf(t4.w, tap(j3), o[c]);
        }
    }
}

// Interior row load: 22 aligned LDG.128 starting at x0-12, stored as two
// predicated STS.64 halves into smem cols 4l-2..4l+1 (col c <-> x0-10+c).
__device__ __forceinline__ void load_row_int(float* s, const float* base,
                                             int y0, int x0, int r, int l) {
    int gy = reflect_idx(y0 - PAD + r, IMG_H);
    if (l < 22) {
        float4 v = __ldg(reinterpret_cast<const float4*>(
            base + (size_t)gy * IMG_W + (x0 - 12)) + l);
        float* row = s + r * SCOLS;
        if (l >= 1)
            *reinterpret_cast<float2*>(row + 4 * l - 2) = make_float2(v.x, v.y);
        if (l <= 20)
            *reinterpret_cast<float2*>(row + 4 * l) = make_float2(v.z, v.w);
    }
}

__device__ __forceinline__ void load_row_edge(float* s, const float* base,
                                              int y0, int x0, int r, int l) {
    int gy = reflect_idx(y0 - PAD + r, IMG_H);
    const float* g = base + (size_t)gy * IMG_W;
    #pragma unroll
    for (int c = l; c < SCOLS; c += 32) {
        int gx = reflect_idx(x0 - PAD + c, IMG_W);
        s[r * SCOLS + c] = __ldg(g + gx);
    }
}

__global__ __launch_bounds__(NTHREADS, 3)
void gauss_blur_fused(const float* __restrict__ in, float* __restrict__ out) {
    extern __shared__ __align__(16) float s[];   // [SROWS][SCOLS]

    const int tid = threadIdx.x;
    const int w = tid >> 5;
    const int l = tid & 31;
    const int x0 = blockIdx.x * TW;
    const int y0 = blockIdx.y * TH;
    const float* __restrict__ base = in + (size_t)blockIdx.z * (IMG_W * IMG_H);

    // interior needs x0-12 >= 0 and x0-12+88 <= 512: same block set as before
    const bool x_int = (x0 >= 12) && (x0 + 76 <= IMG_W);

    // ---- Warp-owned row loading: warp w owns rows 8w..8w+7; warps 0-2 also
    // own tail rows (7/7/6 at 128+7w). ----
    const int r0 = w << 3;
    const int cnt2 = (w == 2) ? 6 : 7;
    const int rb2 = 128 + w * 7;
    if (x_int) {
        #pragma unroll
        for (int rr = 0; rr < 8; ++rr) load_row_int(s, base, y0, x0, r0 + rr, l);
        if (w < 3) {
            #pragma unroll
            for (int rr = 0; rr < 7; ++rr)
                if (rr < cnt2) load_row_int(s, base, y0, x0, rb2 + rr, l);
        }
    } else {
        #pragma unroll
        for (int rr = 0; rr < 8; ++rr) load_row_edge(s, base, y0, x0, r0 + rr, l);
        if (w < 3) {
            #pragma unroll
            for (int rr = 0; rr < 7; ++rr)
                if (rr < cnt2) load_row_edge(s, base, y0, x0, rb2 + rr, l);
        }
    }
    __syncwarp();

    // ---- Horizontal pass, in place, warp-local sync only ----
    // lane = seg*8 + dr: octet = 8 consecutive rows, one seg -> conflict-free.
    const int seg = (l >> 3) << 4;
    const int dr = l & 7;
    {
        const int row = r0 + dr;
        float o[16];
        hfilter16s(&s[row * SCOLS + seg], o);
        __syncwarp();
        float4* q = reinterpret_cast<float4*>(&s[row * SCOLS + seg]);
        q[0] = make_float4(o[0],  o[1],  o[2],  o[3]);
        q[1] = make_float4(o[4],  o[5],  o[6],  o[7]);
        q[2] = make_float4(o[8],  o[9],  o[10], o[11]);
        q[3] = make_float4(o[12], o[13], o[14], o[15]);
    }
    if (w < 3) {   // tail rows, warp-local second round
        const bool act = (dr < cnt2);
        const int row = rb2 + dr;
        float o[16];
        if (act) hfilter16s(&s[row * SCOLS + seg], o);
        __syncwarp();
        if (act) {
            float4* q = reinterpret_cast<float4*>(&s[row * SCOLS + seg]);
            q[0] = make_float4(o[0],  o[1],  o[2],  o[3]);
            q[1] = make_float4(o[4],  o[5],  o[6],  o[7]);
            q[2] = make_float4(o[8],  o[9],  o[10], o[11]);
            q[3] = make_float4(o[12], o[13], o[14], o[15]);
        }
    }

    __syncthreads();   // the ONLY block barrier: h-tile complete

    // ---- Vertical pass: 32 col-pairs x 16 groups of 8 rows ----
    {
        const int cp = tid & 31;
        const int g = (tid >> 5) << 3;

        uint64_t acc[8];
        #pragma unroll
        for (int o = 0; o < 8; ++o) acc[o] = 0;

        const float* col = s + 2 * cp;
        #pragma unroll
        for (int t = 0; t < 28; ++t) {
            uint64_t v2 = *reinterpret_cast<const uint64_t*>(col + (g + t) * SCOLS);
            #pragma unroll
            for (int o = 0; o < 8; ++o) {
                int j = t - o;
                if (j >= 0 && j < KS) {
                    int wi = (j <= 10) ? j : (20 - j);
                    ffma2(acc[o], v2, bcast2(tap(wi)), acc[o]);
                }
            }
        }

        char* dst = (char*)(out + (size_t)blockIdx.z * (IMG_W * IMG_H)
                                + (size_t)(y0 + g) * IMG_W + (x0 + 2 * cp));
        #pragma unroll
        for (int o = 0; o < 8; ++o) {
            *reinterpret_cast<uint64_t*>(dst) = acc[o];
            dst += IMG_W * 4;
        }
    }
}

extern "C" void kernel_launch(void* const* d_in, const int* in_sizes, int n_in,
                              void* d_out, int out_size) {
    (void)in_sizes; (void)n_in; (void)out_size;
    const float* x = (const float*)d_in[0];
    float* y = (float*)d_out;
    cudaFuncSetAttribute(gauss_blur_fused,
                         cudaFuncAttributeMaxDynamicSharedMemorySize, SMEM_BYTES);
    dim3 grid(IMG_W / TW, IMG_H / TH, NIMG);  // 8 x 4 x 96
    gauss_blur_fused<<<grid, NTHREADS, SMEM_BYTES>>>(x, y);
}

// round 16
// speedup vs baseline: 1.4133x; 1.4133x over previous
#include <cuda_runtime.h>
#include <cstdint>

// FixedGaussianBlur: depthwise 21x21 Gaussian (sigma=3), reflect padding,
// x[32,3,512,512] f32 -> y[32,3,512,512] f32.
// R14/R12 skeleton (61.5us best) + producer/consumer named barrier for the
// horizontal tail: only vertical warps 12-15 (groups g>=96, rows >=124) wait
// for tail rows 128-147; warps 3-11 go straight to the vertical pass after
// the main barrier. Warps 0-2 produce tails and bar.arrive (non-blocking).

#define IMG_W 512
#define IMG_H 512
#define PAD 10
#define KS 21
#define TW 64
#define TH 128
#define SROWS 148
#define SCOLS 84
#define NTHREADS 512
#define NIMG 96
#define SMEM_BYTES (SROWS * SCOLS * 4)  // 49728

#define W0  0.13303900f
#define W1  0.12584950f
#define W2  0.10652928f
#define W3  0.08069223f
#define W4  0.05469397f
#define W5  0.03317359f
#define W6  0.01800488f
#define W7  0.00874446f
#define W8  0.00380033f
#define W9  0.00147793f
#define W10 0.00051432f

__device__ __forceinline__ float tap(int j) {
    constexpr float w[KS] = {W10, W9, W8, W7, W6, W5, W4, W3, W2, W1, W0,
                             W1, W2, W3, W4, W5, W6, W7, W8, W9, W10};
    return w[j];
}

__device__ __forceinline__ int reflect_idx(int i, int n) {
    i = (i < 0) ? -i : i;
    i = (i >= n) ? (2 * n - 2 - i) : i;
    return i;
}

__device__ __forceinline__ uint64_t bcast2(float f) {
    uint32_t b = __float_as_uint(f);
    return ((uint64_t)b << 32) | (uint64_t)b;
}

__device__ __forceinline__ void ffma2(uint64_t& d, uint64_t a, uint64_t b, uint64_t c) {
    asm("fma.rn.f32x2 %0, %1, %2, %3;" : "=l"(d) : "l"(a), "l"(b), "l"(c));
}

// Streaming 16-output horizontal filter: 9 LDS.128, each float4 consumed
// immediately into 16 accumulators (liveness ~25 regs).
__device__ __forceinline__ void hfilter16s(const float* srow, float o[16]) {
    #pragma unroll
    for (int c = 0; c < 16; ++c) o[c] = 0.0f;
    const float4* p = reinterpret_cast<const float4*>(srow);
    #pragma unroll
    for (int q = 0; q < 9; ++q) {
        float4 t4 = p[q];
        #pragma unroll
        for (int c = 0; c < 16; ++c) {
            int j0 = 4 * q + 0 - c;
            int j1 = 4 * q + 1 - c;
            int j2 = 4 * q + 2 - c;
            int j3 = 4 * q + 3 - c;
            if (j0 >= 0 && j0 < KS) o[c] = fmaf(t4.x, tap(j0), o[c]);
            if (j1 >= 0 && j1 < KS) o[c] = fmaf(t4.y, tap(j1), o[c]);
            if (j2 >= 0 && j2 < KS) o[c] = fmaf(t4.z, tap(j2), o[c]);
            if (j3 >= 0 && j3 < KS) o[c] = fmaf(t4.w, tap(j3), o[c]);
        }
    }
}

// Load one tile row r from gmem row reflect(y0-PAD+r), warp-cooperative (R12).
__device__ __forceinline__ void load_row_int(float* s, const float* base,
                                             int y0, int x0, int r, int l) {
    int gy = reflect_idx(y0 - PAD + r, IMG_H);
    const uint64_t* g = reinterpret_cast<const uint64_t*>(
        base + (size_t)gy * IMG_W + (x0 - PAD));
    uint64_t* sp = reinterpret_cast<uint64_t*>(s) + r * (SCOLS / 2);
    sp[l] = __ldg(g + l);
    if (l < 10) sp[32 + l] = __ldg(g + 32 + l);
}

__device__ __forceinline__ void load_row_edge(float* s, const float* base,
                                              int y0, int x0, int r, int l) {
    int gy = reflect_idx(y0 - PAD + r, IMG_H);
    const float* g = base + (size_t)gy * IMG_W;
    #pragma unroll
    for (int c = l; c < SCOLS; c += 32) {
        int gx = reflect_idx(x0 - PAD + c, IMG_W);
        s[r * SCOLS + c] = __ldg(g + gx);
    }
}

__global__ __launch_bounds__(NTHREADS, 3)
void gauss_blur_fused(const float* __restrict__ in, float* __restrict__ out) {
    extern __shared__ __align__(16) float s[];   // [SROWS][SCOLS]

    const int tid = threadIdx.x;
    const int w = tid >> 5;
    const int l = tid & 31;
    const int x0 = blockIdx.x * TW;
    const int y0 = blockIdx.y * TH;
    const float* __restrict__ base = in + (size_t)blockIdx.z * (IMG_W * IMG_H);

    const bool x_int = (x0 >= PAD) && (x0 + TW + PAD <= IMG_W);

    // ---- Warp-owned row loading: warp w owns rows 8w..8w+7; warps 0-2 also
    // own tail rows (7/7/6 at 128+7w). ----
    const int r0 = w << 3;
    const int cnt2 = (w == 2) ? 6 : 7;
    const int rb2 = 128 + w * 7;
    if (x_int) {
        #pragma unroll
        for (int rr = 0; rr < 8; ++rr) load_row_int(s, base, y0, x0, r0 + rr, l);
        if (w < 3) {
            #pragma unroll
            for (int rr = 0; rr < 7; ++rr)
                if (rr < cnt2) load_row_int(s, base, y0, x0, rb2 + rr, l);
        }
    } else {
        #pragma unroll
        for (int rr = 0; rr < 8; ++rr) load_row_edge(s, base, y0, x0, r0 + rr, l);
        if (w < 3) {
            #pragma unroll
            for (int rr = 0; rr < 7; ++rr)
                if (rr < cnt2) load_row_edge(s, base, y0, x0, rb2 + rr, l);
        }
    }
    __syncwarp();

    // ---- Horizontal pass, main round: rows 0..127, in place ----
    // lane = seg*8 + dr: octet = 8 consecutive rows, one seg -> conflict-free.
    const int seg = (l >> 3) << 4;
    const int dr = l & 7;
    {
        const int row = r0 + dr;
        float o[16];
        hfilter16s(&s[row * SCOLS + seg], o);
        __syncwarp();
        float4* q = reinterpret_cast<float4*>(&s[row * SCOLS + seg]);
        q[0] = make_float4(o[0],  o[1],  o[2],  o[3]);
        q[1] = make_float4(o[4],  o[5],  o[6],  o[7]);
        q[2] = make_float4(o[8],  o[9],  o[10], o[11]);
        q[3] = make_float4(o[12], o[13], o[14], o[15]);
    }

    __syncthreads();   // main h-rows (0..127) complete, visible to all

    // ---- Tail rows 128..147: produced by warps 0-2, consumed ONLY by
    // vertical warps 12-15 (groups g>=96 read rows 96..147). Producer
    // bar.arrive / consumer bar.sync on named barrier 2 (224 threads). ----
    if (w < 3) {
        const bool act = (dr < cnt2);
        const int row = rb2 + dr;
        float o[16];
        if (act) hfilter16s(&s[row * SCOLS + seg], o);
        __syncwarp();   // tail raw reads done before overwrite (warp-local rows)
        if (act) {
            float4* q = reinterpret_cast<float4*>(&s[row * SCOLS + seg]);
            q[0] = make_float4(o[0],  o[1],  o[2],  o[3]);
            q[1] = make_float4(o[4],  o[5],  o[6],  o[7]);
            q[2] = make_float4(o[8],  o[9],  o[10], o[11]);
            q[3] = make_float4(o[12], o[13], o[14], o[15]);
        }
        asm volatile("bar.arrive 2, 224;" ::: "memory");   // release tails
    } else if (w >= 12) {
        asm volatile("bar.sync 2, 224;" ::: "memory");     // acquire tails
    }
    // warps 3..11 fall through immediately (their rows are all <= 123)

    // ---- Vertical pass: 32 col-pairs x 16 groups of 8 rows ----
    {
        const int cp = tid & 31;
        const int g = (tid >> 5) << 3;   // warp w -> rows 8w..8w+35

        uint64_t acc[8];
        #pragma unroll
        for (int o = 0; o < 8; ++o) acc[o] = 0;

        const float* col = s + 2 * cp;
        #pragma unroll
        for (int t = 0; t < 28; ++t) {
            uint64_t v2 = *reinterpret_cast<const uint64_t*>(col + (g + t) * SCOLS);
            #pragma unroll
            for (int o = 0; o < 8; ++o) {
                int j = t - o;
                if (j >= 0 && j < KS) {
                    int wi = (j <= 10) ? j : (20 - j);
                    ffma2(acc[o], v2, bcast2(tap(wi)), acc[o]);
                }
            }
        }

        char* dst = (char*)(out + (size_t)blockIdx.z * (IMG_W * IMG_H)
                                + (size_t)(y0 + g) * IMG_W + (x0 + 2 * cp));
        #pragma unroll
        for (int o = 0; o < 8; ++o) {
            *reinterpret_cast<uint64_t*>(dst) = acc[o];
            dst += IMG_W * 4;
        }
    }
}

extern "C" void kernel_launch(void* const* d_in, const int* in_sizes, int n_in,
                              void* d_out, int out_size) {
    (void)in_sizes; (void)n_in; (void)out_size;
    const float* x = (const float*)d_in[0];
    float* y = (float*)d_out;
    cudaFuncSetAttribute(gauss_blur_fused,
                         cudaFuncAttributeMaxDynamicSharedMemorySize, SMEM_BYTES);
    dim3 grid(IMG_W / TW, IMG_H / TH, NIMG);  // 8 x 4 x 96
    gauss_blur_fused<<<grid, NTHREADS, SMEM_BYTES>>>(x, y);
}